// round 7
// baseline (speedup 1.0000x reference)
#include <cuda_runtime.h>
#include <math.h>

#define GA 8
#define NB 16384

__device__ float g_comb[NB * 160];
__device__ unsigned g_Wt[128 * 80];   // [BC;E] in tf32 bit patterns, k-major
__device__ float g_AC[6144];          // A+C, stride 96
__device__ float g_W2[96];

__device__ __forceinline__ unsigned long long pack2(float a, float b) {
    unsigned long long r;
    asm("mov.b64 %0, {%1, %2};" : "=l"(r) : "f"(a), "f"(b));
    return r;
}
__device__ __forceinline__ unsigned long long ffma2(unsigned long long a,
                                                    unsigned long long b,
                                                    unsigned long long c) {
    unsigned long long d;
    asm("fma.rn.f32x2 %0, %1, %2, %3;" : "=l"(d) : "l"(a), "l"(b), "l"(c));
    return d;
}
__device__ __forceinline__ void unpack2(unsigned long long v, float& a, float& b) {
    asm("mov.b64 {%0, %1}, %2;" : "=f"(a), "=f"(b) : "l"(v));
}
__device__ __forceinline__ unsigned f2tf32(float f) {
    unsigned u;
    asm("cvt.rna.tf32.f32 %0, %1;" : "=r"(u) : "f"(f));
    return u;
}
__device__ __forceinline__ void mma_tf32(float& c0, float& c1, float& c2, float& c3,
                                         unsigned a0, unsigned a1, unsigned a2, unsigned a3,
                                         unsigned b0, unsigned b1) {
    asm volatile("mma.sync.aligned.m16n8k8.row.col.f32.tf32.tf32.f32 "
                 "{%0,%1,%2,%3}, {%4,%5,%6,%7}, {%8,%9}, {%0,%1,%2,%3};"
                 : "+f"(c0), "+f"(c1), "+f"(c2), "+f"(c3)
                 : "r"(a0), "r"(a1), "r"(a2), "r"(a3), "r"(b0), "r"(b1));
}
__device__ __forceinline__ void cp_async16(float* smem_dst, const float* gsrc) {
    unsigned s = (unsigned)__cvta_generic_to_shared(smem_dst);
    asm volatile("cp.async.cg.shared.global [%0], [%1], 16;" :: "r"(s), "l"(gsrc));
}
__device__ __forceinline__ void cp_async_commit() {
    asm volatile("cp.async.commit_group;");
}
__device__ __forceinline__ void cp_async_wait_all() {
    asm volatile("cp.async.wait_group 0;" ::: "memory");
}

// ---------------------------------------------------------------------------
// Prep: W = [B-C ; E] -> tf32 bits; AC = A+C (stride 96); pad aw2.
// ---------------------------------------------------------------------------
__global__ void din_prep(const float* __restrict__ aw1,
                         const float* __restrict__ aw2) {
    int idx = blockIdx.x * 256 + threadIdx.x;
    if (idx < 10240) {
        int k = idx / 80, j = idx - k * 80;
        float w = (k < 64) ? aw1[(64 + k) * 80 + j] - aw1[(128 + k) * 80 + j]
                           : aw1[(192 + (k - 64)) * 80 + j];
        g_Wt[idx] = f2tf32(w);
    }
    if (idx < 6144) {
        int k = idx / 96, j = idx - k * 96;
        float ac = 0.f;
        if (j < 80)
            ac = aw1[k * 80 + j] + aw1[(128 + k) * 80 + j];
        g_AC[idx] = ac;
    }
    if (blockIdx.x == 0 && threadIdx.x < 96)
        g_W2[threadIdx.x] = (threadIdx.x < 80) ? aw2[threadIdx.x] : 0.f;
}

// ---------------------------------------------------------------------------
// Attention: tf32 mma.sync. GA=8 batches/CTA, 256 thr, 2 CTAs/SM.
// smem floats (26208 total = 104832 B):
//  sW 11264 | sH0 4352 | sH1 4352 | sGq 4352 | sQ 512 | sR 768 | sW2 96
//  sSP 128 | sWt 64 | sPool 256 | sMask 64
// ---------------------------------------------------------------------------
__global__ __launch_bounds__(256, 2)
void din_attention_kernel(
    const int* __restrict__ customer_id,
    const int* __restrict__ cand_good,
    const int* __restrict__ cand_class,
    const int* __restrict__ hist_goods,
    const int* __restrict__ hist_classes,
    const float* __restrict__ user_table,
    const float* __restrict__ item_table,
    const float* __restrict__ cat_table,
    const float* __restrict__ ab1,
    const float* __restrict__ ab2)
{
    extern __shared__ float sm[];
    float*    sWf   = sm;             // 11264 (uints; also AC staging early)
    unsigned* sWu   = (unsigned*)sm;
    float*    sH0   = sm + 11264;     // 4352 (64 rows, stride 68)
    float*    sH1   = sm + 15616;     // 4352
    float*    sGq   = sm + 19968;     // 4352
    float*    sQ    = sm + 24320;     // 512
    float*    sR    = sm + 24832;     // 768
    float*    sW2   = sm + 25600;     // 96
    float*    sSP   = sm + 25696;     // 128 (two n-half partial scores)
    float*    sWt   = sm + 25824;     // 64
    float*    sPool = sm + 25888;     // 256
    int*      sMask = (int*)(sm + 26144); // 64

    const int tid  = threadIdx.x;
    const int warp = tid >> 5;
    const int lane = tid & 31;
    const int gid  = lane >> 2;       // 0..7
    const int tig  = lane & 3;        // 0..3
    const int b0   = blockIdx.x * GA;
    const float ab2v = __ldg(ab2);

    // ---- prefetch H(0) -------------------------------------------------
    {
        const int b = b0;
        #pragma unroll
        for (int i = 0; i < 4; i++) {
            int f4 = tid + 256 * i;
            if (f4 < 800) {
                int l = f4 >> 4, q4 = f4 & 15, d0 = q4 * 4;
                const float* src;
                if (d0 < 32) src = item_table + hist_goods[b * 50 + l] * 32 + d0;
                else         src = cat_table  + hist_classes[b * 50 + l] * 32 + (d0 - 32);
                cp_async16(&sH0[l * 68 + d0], src);
            }
        }
        cp_async_commit();
    }

    // zero pad rows 50..63 of H0/H1/Gq (done once)
    for (int idx = tid; idx < 14 * 64; idx += 256) {
        int l = 50 + (idx >> 6), d = idx & 63;
        sH0[l * 68 + d] = 0.f;
        sH1[l * 68 + d] = 0.f;
        sGq[l * 68 + d] = 0.f;
    }
    if (tid < 96) sW2[tid] = g_W2[tid];

    // q gather + combined[user|cand]
    for (int idx = tid; idx < GA * 64; idx += 256) {
        int g = idx >> 6, d = idx & 63;
        int b = b0 + g;
        float v = (d < 32) ? item_table[cand_good[b] * 32 + d]
                           : cat_table[cand_class[b] * 32 + (d - 32)];
        sQ[idx] = v;
        g_comb[b * 160 + 32 + d] = v;
    }
    for (int idx = tid; idx < GA * 32; idx += 256) {
        int g = idx >> 5, d = idx & 31;
        int b = b0 + g;
        g_comb[b * 160 + d] = user_table[customer_id[b] * 32 + d];
    }

    // stage AC into sW area for the r-vector pass
    #pragma unroll
    for (int i = 0; i < 6; i++) {
        int f4 = tid + 256 * i;
        *(float4*)&sWf[f4 * 4] = __ldg((const float4*)&g_AC[f4 * 4]);
    }
    __syncthreads();

    // r[g][j] = ab1[j] + sum_k q[g][k]*AC[k][j]
    #pragma unroll
    for (int i = 0; i < 3; i++) {
        int idx = tid + 256 * i;
        int g = idx / 96, j = idx - g * 96;
        float v = 0.f;
        if (j < 80) {
            v = __ldg(&ab1[j]);
            #pragma unroll 8
            for (int k = 0; k < 64; k++)
                v += sQ[g * 64 + k] * sWf[k * 96 + j];
        }
        sR[idx] = v;
    }
    __syncthreads();     // AC reads done

    // stage W tf32 (k-major, stride 88): 2560 uint4 loads
    #pragma unroll
    for (int i = 0; i < 10; i++) {
        int f4 = tid + 256 * i;
        int k = f4 / 20, j4 = f4 - k * 20;
        *(uint4*)&sWu[k * 88 + j4 * 4] = __ldg((const uint4*)&g_Wt[k * 80 + j4 * 4]);
    }
    cp_async_wait_all();
    __syncthreads();

    const int mt = warp & 3;          // m16 tile (rows mt*16..mt*16+15)
    const int nh = warp >> 2;         // n-half (cols nh*40..nh*40+39)
    const int r_lo = mt * 16 + gid;

    for (int g = 0; g < GA; g++) {
        const int b = b0 + g;
        float* sHc = (g & 1) ? sH1 : sH0;
        float* sHa = (g & 1) ? sH0 : sH1;

        // prefetch H(g+1)
        if (g < 7) {
            const int bn = b + 1;
            #pragma unroll
            for (int i = 0; i < 4; i++) {
                int f4 = tid + 256 * i;
                if (f4 < 800) {
                    int l = f4 >> 4, q4 = f4 & 15, d0 = q4 * 4;
                    const float* src;
                    if (d0 < 32) src = item_table + hist_goods[bn * 50 + l] * 32 + d0;
                    else         src = cat_table  + hist_classes[bn * 50 + l] * 32 + (d0 - 32);
                    cp_async16(&sHa[l * 68 + d0], src);
                }
            }
            cp_async_commit();
        }
        // masks for this batch
        if (tid < 50) sMask[tid] = hist_goods[b * 50 + tid];

        // build Gq = tf32(q * H) for rows 0..49
        for (int f = tid; f < 3200; f += 256) {
            int l = f >> 6, k = f & 63;
            sGq[l * 68 + k] = __uint_as_float(f2tf32(sQ[g * 64 + k] * sHc[l * 68 + k]));
        }
        __syncthreads();   // sync1: Gq ready

        // ---- MMA: warp computes m16 x n40 over K=128 -------------------
        {
            float acc[5][4];
            #pragma unroll
            for (int nt = 0; nt < 5; nt++)
                acc[nt][0] = acc[nt][1] = acc[nt][2] = acc[nt][3] = 0.f;

            #pragma unroll
            for (int ks = 0; ks < 16; ks++) {
                const float* srcA = (ks < 8) ? sHc : sGq;
                const int kc = (ks & 7) * 8 + tig;
                unsigned a0 = __float_as_uint(srcA[r_lo * 68 + kc]);
                unsigned a1 = __float_as_uint(srcA[(r_lo + 8) * 68 + kc]);
                unsigned a2 = __float_as_uint(srcA[r_lo * 68 + kc + 4]);
                unsigned a3 = __float_as_uint(srcA[(r_lo + 8) * 68 + kc + 4]);
                const int k0 = ks * 8;
                #pragma unroll
                for (int nt = 0; nt < 5; nt++) {
                    const int nc = (nh * 5 + nt) * 8 + gid;
                    unsigned b0r = sWu[(k0 + tig) * 88 + nc];
                    unsigned b1r = sWu[(k0 + tig + 4) * 88 + nc];
                    mma_tf32(acc[nt][0], acc[nt][1], acc[nt][2], acc[nt][3],
                             a0, a1, a2, a3, b0r, b1r);
                }
            }

            // epilogue: relu(S + r) . w2 -> per-row partial score
            float slo = 0.f, shi = 0.f;
            #pragma unroll
            for (int nt = 0; nt < 5; nt++) {
                const int j0 = (nh * 5 + nt) * 8 + tig * 2;
                float r0v = sR[g * 96 + j0], r1v = sR[g * 96 + j0 + 1];
                float w0 = sW2[j0], w1 = sW2[j0 + 1];
                slo += fmaxf(acc[nt][0] + r0v, 0.f) * w0
                     + fmaxf(acc[nt][1] + r1v, 0.f) * w1;
                shi += fmaxf(acc[nt][2] + r0v, 0.f) * w0
                     + fmaxf(acc[nt][3] + r1v, 0.f) * w1;
            }
            slo += __shfl_down_sync(0xFFFFFFFFu, slo, 2, 4);
            slo += __shfl_down_sync(0xFFFFFFFFu, slo, 1, 4);
            shi += __shfl_down_sync(0xFFFFFFFFu, shi, 2, 4);
            shi += __shfl_down_sync(0xFFFFFFFFu, shi, 1, 4);
            if (tig == 0) {
                sSP[nh * 64 + r_lo] = slo;
                sSP[nh * 64 + r_lo + 8] = shi;
            }
        }
        __syncthreads();   // sync2: partial scores ready

        // softmax (warp 0)
        if (warp == 0) {
            float s0 = -INFINITY, s1 = -INFINITY;
            if (lane < 50) {
                s0 = sSP[lane] + sSP[64 + lane] + ab2v;
                if (sMask[lane] == 0) s0 = -1e9f;
            }
            if (lane + 32 < 50) {
                s1 = sSP[lane + 32] + sSP[96 + lane] + ab2v;
                if (sMask[lane + 32] == 0) s1 = -1e9f;
            }
            float mx = fmaxf(s0, s1);
            #pragma unroll
            for (int o = 16; o > 0; o >>= 1)
                mx = fmaxf(mx, __shfl_xor_sync(0xFFFFFFFFu, mx, o));
            float e0 = (lane < 50) ? expf(s0 - mx) : 0.f;
            float e1 = (lane + 32 < 50) ? expf(s1 - mx) : 0.f;
            float sum = e0 + e1;
            #pragma unroll
            for (int o = 16; o > 0; o >>= 1)
                sum += __shfl_xor_sync(0xFFFFFFFFu, sum, o);
            float inv = 1.f / sum;
            if (lane < 50) sWt[lane] = e0 * inv;
            if (lane + 32 < 50) sWt[lane + 32] = e1 * inv;
        }
        __syncthreads();   // sync3: weights ready

        // pooling: 256 threads (4 l-chunks x 64 d)
        {
            int lq = tid >> 6, d = tid & 63;
            int l0 = lq * 13, l1 = min(l0 + 13, 50);
            float p = 0.f;
            for (int l = l0; l < l1; l++) p += sWt[l] * sHc[l * 68 + d];
            sPool[lq * 64 + d] = p;
        }
        __syncthreads();   // sync4
        if (tid < 64)
            g_comb[b * 160 + 96 + tid] =
                sPool[tid] + sPool[64 + tid] + sPool[128 + tid] + sPool[192 + tid];
        if (g < 7) cp_async_wait_all();
        __syncthreads();   // sync5: H(g+1) landed, buffers free
    }
}

// ---------------------------------------------------------------------------
// MLP 160 -> 256 -> 128 -> 1 (unchanged from R3). 32 rows/CTA, 3 CTAs/SM.
// ---------------------------------------------------------------------------
__global__ __launch_bounds__(256, 3)
void din_mlp_kernel(const float* __restrict__ mw1, const float* __restrict__ mb1,
                    const float* __restrict__ mw2, const float* __restrict__ mb2,
                    const float* __restrict__ mw3, const float* __restrict__ mb3,
                    float* __restrict__ out)
{
    extern __shared__ float sm[];
    float* sX  = sm;            // 5248
    float* sW  = sm + 5248;     // 4160
    float* sZ1 = sm + 9408;     // 8320
    float* sW3 = sm + 17728;    // 128

    const int tid = threadIdx.x;
    const int b0  = blockIdx.x * 32;

    for (int f = tid; f < 1280; f += 256) {
        int row = f / 40, c4 = f - row * 40;
        *(float4*)&sX[row * 164 + c4 * 4] =
            *(const float4*)&g_comb[(b0 + row) * 160 + c4 * 4];
    }
    if (tid < 128) sW3[tid] = mw3[tid];

    const int half = tid >> 7;
    const int t    = tid & 127;
    const int rp   = t >> 3;
    const int c0   = t & 7;
    const int r0   = rp * 2;
    const int jb1  = half * 128 + c0 * 4;
    const int jb2  = half * 64  + c0 * 4;

    unsigned long long acc1[2][8];
    #pragma unroll
    for (int u = 0; u < 4; u++) {
        ulonglong2 bb = *(const ulonglong2*)&mb1[jb1 + u * 32];
        acc1[0][2*u] = bb.x; acc1[0][2*u+1] = bb.y;
        acc1[1][2*u] = bb.x; acc1[1][2*u+1] = bb.y;
    }
    float4 pf[4];
    #pragma unroll
    for (int i = 0; i < 4; i++)
        pf[i] = *(const float4*)&mw1[tid * 4 + i * 1024];

    for (int s = 0; s < 10; s++) {
        #pragma unroll
        for (int i = 0; i < 4; i++) {
            int o = tid * 4 + i * 1024;
            *(float4*)&sW[(o >> 8) * 260 + (o & 255)] = pf[i];
        }
        __syncthreads();
        if (s < 9) {
            const float* src = mw1 + (s + 1) * 4096;
            #pragma unroll
            for (int i = 0; i < 4; i++)
                pf[i] = *(const float4*)&src[tid * 4 + i * 1024];
        }
        const int xb = s * 16;
        #pragma unroll 4
        for (int kk = 0; kk < 16; kk++) {
            float x0 = sX[r0 * 164 + xb + kk];
            float x1 = sX[(r0 + 1) * 164 + xb + kk];
            unsigned long long xr0 = pack2(x0, x0);
            unsigned long long xr1 = pack2(x1, x1);
            #pragma unroll
            for (int u = 0; u < 4; u++) {
                ulonglong2 w = *(const ulonglong2*)&sW[kk * 260 + jb1 + u * 32];
                acc1[0][2*u]   = ffma2(xr0, w.x, acc1[0][2*u]);
                acc1[0][2*u+1] = ffma2(xr0, w.y, acc1[0][2*u+1]);
                acc1[1][2*u]   = ffma2(xr1, w.x, acc1[1][2*u]);
                acc1[1][2*u+1] = ffma2(xr1, w.y, acc1[1][2*u+1]);
            }
        }
        __syncthreads();
    }
    #pragma unroll
    for (int r = 0; r < 2; r++)
        #pragma unroll
        for (int u = 0; u < 4; u++) {
            float v0, v1, v2, v3;
            unpack2(acc1[r][2*u], v0, v1); unpack2(acc1[r][2*u+1], v2, v3);
            float4 z = make_float4(fmaxf(v0, 0.f), fmaxf(v1, 0.f),
                                   fmaxf(v2, 0.f), fmaxf(v3, 0.f));
            *(float4*)&sZ1[(r0 + r) * 260 + jb1 + u * 32] = z;
        }

    unsigned long long acc2[2][4];
    #pragma unroll
    for (int u = 0; u < 2; u++) {
        ulonglong2 bb = *(const ulonglong2*)&mb2[jb2 + u * 32];
        acc2[0][2*u] = bb.x; acc2[0][2*u+1] = bb.y;
        acc2[1][2*u] = bb.x; acc2[1][2*u+1] = bb.y;
    }
    float4 pg[2];
    #pragma unroll
    for (int i = 0; i < 2; i++)
        pg[i] = *(const float4*)&mw2[tid * 4 + i * 1024];

    for (int s = 0; s < 16; s++) {
        #pragma unroll
        for (int i = 0; i < 2; i++) {
            int o = tid * 4 + i * 1024;
            *(float4*)&sW[(o >> 7) * 132 + (o & 127)] = pg[i];
        }
        __syncthreads();
        if (s < 15) {
            const float* src = mw2 + (s + 1) * 2048;
            #pragma unroll
            for (int i = 0; i < 2; i++)
                pg[i] = *(const float4*)&src[tid * 4 + i * 1024];
        }
        const int xb = s * 16;
        #pragma unroll 4
        for (int kk = 0; kk < 16; kk++) {
            float x0 = sZ1[r0 * 260 + xb + kk];
            float x1 = sZ1[(r0 + 1) * 260 + xb + kk];
            unsigned long long xr0 = pack2(x0, x0);
            unsigned long long xr1 = pack2(x1, x1);
            #pragma unroll
            for (int u = 0; u < 2; u++) {
                ulonglong2 w = *(const ulonglong2*)&sW[kk * 132 + jb2 + u * 32];
                acc2[0][2*u]   = ffma2(xr0, w.x, acc2[0][2*u]);
                acc2[0][2*u+1] = ffma2(xr0, w.y, acc2[0][2*u+1]);
                acc2[1][2*u]   = ffma2(xr1, w.x, acc2[1][2*u]);
                acc2[1][2*u+1] = ffma2(xr1, w.y, acc2[1][2*u+1]);
            }
        }
        __syncthreads();
    }
    #pragma unroll
    for (int r = 0; r < 2; r++)
        #pragma unroll
        for (int u = 0; u < 2; u++) {
            float v0, v1, v2, v3;
            unpack2(acc2[r][2*u], v0, v1); unpack2(acc2[r][2*u+1], v2, v3);
            float4 z = make_float4(fmaxf(v0, 0.f), fmaxf(v1, 0.f),
                                   fmaxf(v2, 0.f), fmaxf(v3, 0.f));
            *(float4*)&sX[(r0 + r) * 132 + jb2 + u * 32] = z;
        }
    __syncthreads();

    {
        int row = tid >> 3, seg = tid & 7;
        float p = 0.f;
        #pragma unroll
        for (int k = seg * 16; k < seg * 16 + 16; k++)
            p += sX[row * 132 + k] * sW3[k];
        #pragma unroll
        for (int o = 4; o > 0; o >>= 1)
            p += __shfl_down_sync(0xFFFFFFFFu, p, o, 8);
        if (seg == 0) out[b0 + row] = p + mb3[0];
    }
}

// ---------------------------------------------------------------------------
extern "C" void kernel_launch(void* const* d_in, const int* in_sizes, int n_in,
                              void* d_out, int out_size) {
    const int*   customer_id  = (const int*)d_in[0];
    const int*   cand_good    = (const int*)d_in[1];
    const int*   cand_class   = (const int*)d_in[2];
    const int*   hist_goods   = (const int*)d_in[3];
    const int*   hist_classes = (const int*)d_in[4];
    const float* user_table   = (const float*)d_in[5];
    const float* item_table   = (const float*)d_in[6];
    const float* cat_table    = (const float*)d_in[7];
    const float* aw1 = (const float*)d_in[8];
    const float* ab1 = (const float*)d_in[9];
    const float* aw2 = (const float*)d_in[10];
    const float* ab2 = (const float*)d_in[11];
    const float* mw1 = (const float*)d_in[12];
    const float* mb1 = (const float*)d_in[13];
    const float* mw2 = (const float*)d_in[14];
    const float* mb2 = (const float*)d_in[15];
    const float* mw3 = (const float*)d_in[16];
    const float* mb3 = (const float*)d_in[17];

    const int smemA = 26208 * 4;
    const int smemB = 17856 * 4;
    cudaFuncSetAttribute(din_attention_kernel,
                         cudaFuncAttributeMaxDynamicSharedMemorySize, smemA);
    cudaFuncSetAttribute(din_mlp_kernel,
                         cudaFuncAttributeMaxDynamicSharedMemorySize, smemB);

    din_prep<<<40, 256>>>(aw1, aw2);

    din_attention_kernel<<<NB / GA, 256, smemA>>>(
        customer_id, cand_good, cand_class, hist_goods, hist_classes,
        user_table, item_table, cat_table, ab1, ab2);

    din_mlp_kernel<<<NB / 32, 256, smemB>>>(
        mw1, mb1, mw2, mb2, mw3, mb3, (float*)d_out);
}

// round 9
// speedup vs baseline: 1.9460x; 1.9460x over previous
#include <cuda_runtime.h>
#include <math.h>

#define GA 8
#define NB 16384

__device__ float g_comb[NB * 160];
__device__ uint2 g_P[5120];      // packed tf32 B-frag pairs [64 rows][80 n]
__device__ float g_AC[5120];     // A+C, [64 k][80 j]
__device__ float g_W2[80];

__device__ __forceinline__ unsigned long long pack2(float a, float b) {
    unsigned long long r;
    asm("mov.b64 %0, {%1, %2};" : "=l"(r) : "f"(a), "f"(b));
    return r;
}
__device__ __forceinline__ unsigned long long ffma2(unsigned long long a,
                                                    unsigned long long b,
                                                    unsigned long long c) {
    unsigned long long d;
    asm("fma.rn.f32x2 %0, %1, %2, %3;" : "=l"(d) : "l"(a), "l"(b), "l"(c));
    return d;
}
__device__ __forceinline__ void unpack2(unsigned long long v, float& a, float& b) {
    asm("mov.b64 {%0, %1}, %2;" : "=f"(a), "=f"(b) : "l"(v));
}
__device__ __forceinline__ unsigned f2tf32(float f) {
    unsigned u;
    asm("cvt.rna.tf32.f32 %0, %1;" : "=r"(u) : "f"(f));
    return u;
}
__device__ __forceinline__ void mma_tf32(float& c0, float& c1, float& c2, float& c3,
                                         unsigned a0, unsigned a1, unsigned a2, unsigned a3,
                                         unsigned b0, unsigned b1) {
    asm volatile("mma.sync.aligned.m16n8k8.row.col.f32.tf32.tf32.f32 "
                 "{%0,%1,%2,%3}, {%4,%5,%6,%7}, {%8,%9}, {%0,%1,%2,%3};"
                 : "+f"(c0), "+f"(c1), "+f"(c2), "+f"(c3)
                 : "r"(a0), "r"(a1), "r"(a2), "r"(a3), "r"(b0), "r"(b1));
}
__device__ __forceinline__ void cp_async16(float* smem_dst, const float* gsrc) {
    unsigned s = (unsigned)__cvta_generic_to_shared(smem_dst);
    asm volatile("cp.async.cg.shared.global [%0], [%1], 16;" :: "r"(s), "l"(gsrc));
}
__device__ __forceinline__ void cp_async_commit() {
    asm volatile("cp.async.commit_group;");
}
__device__ __forceinline__ void cp_async_wait_all() {
    asm volatile("cp.async.wait_group 0;" ::: "memory");
}
__device__ __forceinline__ void bar_grp(int id) {
    asm volatile("bar.sync %0, %1;" :: "r"(id), "r"(128) : "memory");
}

// ---------------------------------------------------------------------------
// Prep: pack W=[B-C;E] as tf32 (k,k+4) uint2 pairs in mma B-frag row order;
// AC = A+C; copy aw2.
// Row r of g_P: halfK = r>>5, ks = (r>>2)&7, tg = r&3; pair k = ks*8+tg, +4.
// ---------------------------------------------------------------------------
__global__ void din_prep(const float* __restrict__ aw1,
                         const float* __restrict__ aw2) {
    int idx = blockIdx.x * 256 + threadIdx.x;
    if (idx < 5120) {
        int r = idx / 80, n = idx - r * 80;
        int halfK = r >> 5, rr = r & 31, ks = rr >> 2, tg = rr & 3;
        int k1 = ks * 8 + tg, k2 = k1 + 4;
        float wa, wb;
        if (halfK == 0) {
            wa = aw1[(64 + k1) * 80 + n] - aw1[(128 + k1) * 80 + n];
            wb = aw1[(64 + k2) * 80 + n] - aw1[(128 + k2) * 80 + n];
        } else {
            wa = aw1[(192 + k1) * 80 + n];
            wb = aw1[(192 + k2) * 80 + n];
        }
        g_P[idx] = make_uint2(f2tf32(wa), f2tf32(wb));
        // AC uses same idx mapping: k = idx/80, j = n
        g_AC[idx] = aw1[r * 80 + n] + aw1[(128 + r) * 80 + n];
    }
    if (idx < 80) g_W2[idx] = aw2[idx];
}

// ---------------------------------------------------------------------------
// Attention: tf32 mma, warp-per-m-tile, two independent 128-thread groups.
// smem (floats, 28272 total = 113088 B, 2 CTAs/SM):
//  sP 10752 (64 rows x 168 words, uint2 stride 84) | sH 4x3808 + 544 tail
//  sQ 512 | sR 640 | sW2 80 | sScore 128 | sWt 128 | sPool 256
// ---------------------------------------------------------------------------
__global__ __launch_bounds__(256, 2)
void din_attention_kernel(
    const int* __restrict__ customer_id,
    const int* __restrict__ cand_good,
    const int* __restrict__ cand_class,
    const int* __restrict__ hist_goods,
    const int* __restrict__ hist_classes,
    const float* __restrict__ user_table,
    const float* __restrict__ item_table,
    const float* __restrict__ cat_table,
    const float* __restrict__ ab1,
    const float* __restrict__ ab2)
{
    extern __shared__ float sm[];
    uint2* sPu2   = (uint2*)sm;        // words 0..10752
    float* sH     = sm + 10752;        // 4 x 3808 (+544 overflow tail)
    float* sQ     = sm + 26528;        // 512
    float* sR     = sm + 27040;        // 640 (stride 80)
    float* sW2    = sm + 27680;        // 80
    float* sScore = sm + 27760;        // 2 x 64
    float* sWt    = sm + 27888;        // 2 x 64
    float* sPool  = sm + 28016;        // 2 x 128

    const int tid  = threadIdx.x;
    const int warp = tid >> 5;
    const int lane = tid & 31;
    const int gid  = lane >> 2;        // 0..7
    const int tig  = lane & 3;         // 0..3
    const int grp  = warp >> 2;        // 0 or 1
    const int mt   = warp & 3;         // m16 tile
    const int tg128 = tid & 127;
    const int b0   = blockIdx.x * GA;
    const float ab2v = __ldg(ab2);

    // ================= Phase A (CTA-wide, once) =========================
    // q gather + combined[user|cand]
    for (int idx = tid; idx < GA * 64; idx += 256) {
        int g = idx >> 6, d = idx & 63;
        int b = b0 + g;
        float v = (d < 32) ? item_table[cand_good[b] * 32 + d]
                           : cat_table[cand_class[b] * 32 + (d - 32)];
        sQ[idx] = v;
        g_comb[b * 160 + 32 + d] = v;
    }
    for (int idx = tid; idx < GA * 32; idx += 256) {
        int g = idx >> 5, d = idx & 31;
        int b = b0 + g;
        g_comb[b * 160 + d] = user_table[customer_id[b] * 32 + d];
    }
    // stage AC into sH region (stride 80), copy packed W into sP (re-stride)
    float* sAC = sH;
    #pragma unroll
    for (int i = 0; i < 5; i++) {
        int f4 = tid + 256 * i;   // 1280 float4
        *(float4*)&sAC[f4 * 4] = __ldg((const float4*)g_AC + f4);
    }
    if (tid < 80) sW2[tid] = g_W2[tid];
    #pragma unroll
    for (int i = 0; i < 10; i++) {
        int v = tid + 256 * i;    // 2560 uint4
        int row = v / 40, n2 = v - row * 40;
        ((uint4*)sm)[row * 42 + n2] = __ldg((const uint4*)g_P + row * 40 + n2);
    }
    __syncthreads();
    // r[g][j] = ab1[j] + sum_k q[g][k]*AC[k][j]   (640 outputs)
    for (int idx = tid; idx < 640; idx += 256) {
        int g = idx / 80, j = idx - g * 80;
        float v = __ldg(&ab1[j]);
        #pragma unroll 8
        for (int k = 0; k < 64; k++)
            v += sQ[g * 64 + k] * sAC[k * 80 + j];
        sR[idx] = v;
    }
    __syncthreads();   // sP, sR ready; sAC region free for H buffers

    // ================= Phase B (two independent groups) =================
    const int barid = grp + 1;
    float* bufA = sH + (grp * 2) * 3808;
    float* bufB = sH + (grp * 2 + 1) * 3808;
    const int gfirst = grp * 4;

    // prefetch H(first batch of group)
    {
        const int b = b0 + gfirst;
        for (int f4 = tg128; f4 < 800; f4 += 128) {
            int l = f4 >> 4, q4 = f4 & 15, d0 = q4 * 4;
            const float* src;
            if (d0 < 32) src = item_table + hist_goods[b * 50 + l] * 32 + d0;
            else         src = cat_table  + hist_classes[b * 50 + l] * 32 + (d0 - 32);
            cp_async16(&bufA[l * 68 + d0], src);
        }
        cp_async_commit();
        cp_async_wait_all();
        bar_grp(barid);
    }

    const int r_lo = mt * 16 + gid;
    const int r_hi = r_lo + 8;

    for (int i = 0; i < 4; i++) {
        const int gg = gfirst + i;         // batch index within CTA
        const int b  = b0 + gg;
        float* Hc = (i & 1) ? bufB : bufA;
        float* Ha = (i & 1) ? bufA : bufB;

        // prefetch H(next)
        if (i < 3) {
            const int bn = b + 1;
            for (int f4 = tg128; f4 < 800; f4 += 128) {
                int l = f4 >> 4, q4 = f4 & 15, d0 = q4 * 4;
                const float* src;
                if (d0 < 32) src = item_table + hist_goods[bn * 50 + l] * 32 + d0;
                else         src = cat_table  + hist_classes[bn * 50 + l] * 32 + (d0 - 32);
                cp_async16(&Ha[l * 68 + d0], src);
            }
            cp_async_commit();
        }
        // mask prefetch (only score-writing lanes)
        int mk0 = 1, mk1 = 1;
        if (tig == 0) {
            if (r_lo < 50) mk0 = hist_goods[b * 50 + r_lo];
            if (r_hi < 50) mk1 = hist_goods[b * 50 + r_hi];
        }

        // ---- MMA: this warp = rows [mt*16, mt*16+16), all n=80, K=128 ----
        float acc[10][4];
        #pragma unroll
        for (int nt = 0; nt < 10; nt++)
            acc[nt][0] = acc[nt][1] = acc[nt][2] = acc[nt][3] = 0.f;

        #pragma unroll
        for (int ks = 0; ks < 8; ks++) {
            const int kc = ks * 8 + tig;
            float a0f = Hc[r_lo * 68 + kc];
            float a1f = Hc[r_hi * 68 + kc];
            float a2f = Hc[r_lo * 68 + kc + 4];
            float a3f = Hc[r_hi * 68 + kc + 4];
            unsigned a0 = __float_as_uint(a0f), a1 = __float_as_uint(a1f);
            unsigned a2 = __float_as_uint(a2f), a3 = __float_as_uint(a3f);
            const uint2* P0 = sPu2 + (ks * 4 + tig) * 84;
            #pragma unroll
            for (int nt = 0; nt < 10; nt++) {
                uint2 bb = P0[nt * 8 + gid];
                mma_tf32(acc[nt][0], acc[nt][1], acc[nt][2], acc[nt][3],
                         a0, a1, a2, a3, bb.x, bb.y);
            }
            float ql = sQ[gg * 64 + kc], qh = sQ[gg * 64 + kc + 4];
            unsigned g0 = f2tf32(a0f * ql), g1 = f2tf32(a1f * ql);
            unsigned g2 = f2tf32(a2f * qh), g3 = f2tf32(a3f * qh);
            const uint2* P1 = sPu2 + (32 + ks * 4 + tig) * 84;
            #pragma unroll
            for (int nt = 0; nt < 10; nt++) {
                uint2 bb = P1[nt * 8 + gid];
                mma_tf32(acc[nt][0], acc[nt][1], acc[nt][2], acc[nt][3],
                         g0, g1, g2, g3, bb.x, bb.y);
            }
        }

        // ---- epilogue: score = relu(S + r) . w2, reduce over tig ---------
        float slo = 0.f, shi = 0.f;
        #pragma unroll
        for (int nt = 0; nt < 10; nt++) {
            const int j0 = nt * 8 + tig * 2;
            float r0v = sR[gg * 80 + j0], r1v = sR[gg * 80 + j0 + 1];
            float w0 = sW2[j0], w1 = sW2[j0 + 1];
            slo += fmaxf(acc[nt][0] + r0v, 0.f) * w0
                 + fmaxf(acc[nt][1] + r1v, 0.f) * w1;
            shi += fmaxf(acc[nt][2] + r0v, 0.f) * w0
                 + fmaxf(acc[nt][3] + r1v, 0.f) * w1;
        }
        slo += __shfl_down_sync(0xFFFFFFFFu, slo, 2, 4);
        slo += __shfl_down_sync(0xFFFFFFFFu, slo, 1, 4);
        shi += __shfl_down_sync(0xFFFFFFFFu, shi, 2, 4);
        shi += __shfl_down_sync(0xFFFFFFFFu, shi, 1, 4);
        if (tig == 0) {
            if (r_lo < 50)
                sScore[grp * 64 + r_lo] = (mk0 == 0) ? -1e9f : slo + ab2v;
            if (r_hi < 50)
                sScore[grp * 64 + r_hi] = (mk1 == 0) ? -1e9f : shi + ab2v;
        }
        bar_grp(barid);   // bar1: scores ready

        // ---- softmax (warp mt==0 of group) -------------------------------
        if (mt == 0) {
            float s0 = (lane < 50) ? sScore[grp * 64 + lane] : -INFINITY;
            float s1 = (lane + 32 < 50) ? sScore[grp * 64 + lane + 32] : -INFINITY;
            float mx = fmaxf(s0, s1);
            #pragma unroll
            for (int o = 16; o > 0; o >>= 1)
                mx = fmaxf(mx, __shfl_xor_sync(0xFFFFFFFFu, mx, o));
            float e0 = (lane < 50) ? expf(s0 - mx) : 0.f;
            float e1 = (lane + 32 < 50) ? expf(s1 - mx) : 0.f;
            float sum = e0 + e1;
            #pragma unroll
            for (int o = 16; o > 0; o >>= 1)
                sum += __shfl_xor_sync(0xFFFFFFFFu, sum, o);
            float inv = 1.f / sum;
            if (lane < 50) sWt[grp * 64 + lane] = e0 * inv;
            if (lane + 32 < 50) sWt[grp * 64 + lane + 32] = e1 * inv;
        }
        bar_grp(barid);   // bar2: weights ready

        // ---- pooling: 128 threads, d = t&63, half the l-range each -------
        {
            int d = tg128 & 63, lh = tg128 >> 6;
            int l0 = lh * 25;
            float p = 0.f;
            #pragma unroll 5
            for (int l = l0; l < l0 + 25; l++)
                p += sWt[grp * 64 + l] * Hc[l * 68 + d];
            sPool[grp * 128 + tg128] = p;
        }
        if (i < 3) cp_async_wait_all();
        bar_grp(barid);   // bar3: pool partials + next H ready
        if (tg128 < 64)
            g_comb[b * 160 + 96 + tg128] =
                sPool[grp * 128 + tg128] + sPool[grp * 128 + 64 + tg128];
    }
}

// ---------------------------------------------------------------------------
// MLP 160 -> 256 -> 128 -> 1 (unchanged, R2-verified). 32 rows/CTA, 3 CTAs/SM.
// ---------------------------------------------------------------------------
__global__ __launch_bounds__(256, 3)
void din_mlp_kernel(const float* __restrict__ mw1, const float* __restrict__ mb1,
                    const float* __restrict__ mw2, const float* __restrict__ mb2,
                    const float* __restrict__ mw3, const float* __restrict__ mb3,
                    float* __restrict__ out)
{
    extern __shared__ float sm[];
    float* sX  = sm;            // 5248
    float* sW  = sm + 5248;     // 4160
    float* sZ1 = sm + 9408;     // 8320
    float* sW3 = sm + 17728;    // 128

    const int tid = threadIdx.x;
    const int b0  = blockIdx.x * 32;

    for (int f = tid; f < 1280; f += 256) {
        int row = f / 40, c4 = f - row * 40;
        *(float4*)&sX[row * 164 + c4 * 4] =
            *(const float4*)&g_comb[(b0 + row) * 160 + c4 * 4];
    }
    if (tid < 128) sW3[tid] = mw3[tid];

    const int half = tid >> 7;
    const int t    = tid & 127;
    const int rp   = t >> 3;
    const int c0   = t & 7;
    const int r0   = rp * 2;
    const int jb1  = half * 128 + c0 * 4;
    const int jb2  = half * 64  + c0 * 4;

    unsigned long long acc1[2][8];
    #pragma unroll
    for (int u = 0; u < 4; u++) {
        ulonglong2 bb = *(const ulonglong2*)&mb1[jb1 + u * 32];
        acc1[0][2*u] = bb.x; acc1[0][2*u+1] = bb.y;
        acc1[1][2*u] = bb.x; acc1[1][2*u+1] = bb.y;
    }
    float4 pf[4];
    #pragma unroll
    for (int i = 0; i < 4; i++)
        pf[i] = *(const float4*)&mw1[tid * 4 + i * 1024];

    for (int s = 0; s < 10; s++) {
        #pragma unroll
        for (int i = 0; i < 4; i++) {
            int o = tid * 4 + i * 1024;
            *(float4*)&sW[(o >> 8) * 260 + (o & 255)] = pf[i];
        }
        __syncthreads();
        if (s < 9) {
            const float* src = mw1 + (s + 1) * 4096;
            #pragma unroll
            for (int i = 0; i < 4; i++)
                pf[i] = *(const float4*)&src[tid * 4 + i * 1024];
        }
        const int xb = s * 16;
        #pragma unroll 4
        for (int kk = 0; kk < 16; kk++) {
            float x0 = sX[r0 * 164 + xb + kk];
            float x1 = sX[(r0 + 1) * 164 + xb + kk];
            unsigned long long xr0 = pack2(x0, x0);
            unsigned long long xr1 = pack2(x1, x1);
            #pragma unroll
            for (int u = 0; u < 4; u++) {
                ulonglong2 w = *(const ulonglong2*)&sW[kk * 260 + jb1 + u * 32];
                acc1[0][2*u]   = ffma2(xr0, w.x, acc1[0][2*u]);
                acc1[0][2*u+1] = ffma2(xr0, w.y, acc1[0][2*u+1]);
                acc1[1][2*u]   = ffma2(xr1, w.x, acc1[1][2*u]);
                acc1[1][2*u+1] = ffma2(xr1, w.y, acc1[1][2*u+1]);
            }
        }
        __syncthreads();
    }
    #pragma unroll
    for (int r = 0; r < 2; r++)
        #pragma unroll
        for (int u = 0; u < 4; u++) {
            float v0, v1, v2, v3;
            unpack2(acc1[r][2*u], v0, v1); unpack2(acc1[r][2*u+1], v2, v3);
            float4 z = make_float4(fmaxf(v0, 0.f), fmaxf(v1, 0.f),
                                   fmaxf(v2, 0.f), fmaxf(v3, 0.f));
            *(float4*)&sZ1[(r0 + r) * 260 + jb1 + u * 32] = z;
        }

    unsigned long long acc2[2][4];
    #pragma unroll
    for (int u = 0; u < 2; u++) {
        ulonglong2 bb = *(const ulonglong2*)&mb2[jb2 + u * 32];
        acc2[0][2*u] = bb.x; acc2[0][2*u+1] = bb.y;
        acc2[1][2*u] = bb.x; acc2[1][2*u+1] = bb.y;
    }
    float4 pg[2];
    #pragma unroll
    for (int i = 0; i < 2; i++)
        pg[i] = *(const float4*)&mw2[tid * 4 + i * 1024];

    for (int s = 0; s < 16; s++) {
        #pragma unroll
        for (int i = 0; i < 2; i++) {
            int o = tid * 4 + i * 1024;
            *(float4*)&sW[(o >> 7) * 132 + (o & 127)] = pg[i];
        }
        __syncthreads();
        if (s < 15) {
            const float* src = mw2 + (s + 1) * 2048;
            #pragma unroll
            for (int i = 0; i < 2; i++)
                pg[i] = *(const float4*)&src[tid * 4 + i * 1024];
        }
        const int xb = s * 16;
        #pragma unroll 4
        for (int kk = 0; kk < 16; kk++) {
            float x0 = sZ1[r0 * 260 + xb + kk];
            float x1 = sZ1[(r0 + 1) * 260 + xb + kk];
            unsigned long long xr0 = pack2(x0, x0);
            unsigned long long xr1 = pack2(x1, x1);
            #pragma unroll
            for (int u = 0; u < 2; u++) {
                ulonglong2 w = *(const ulonglong2*)&sW[kk * 132 + jb2 + u * 32];
                acc2[0][2*u]   = ffma2(xr0, w.x, acc2[0][2*u]);
                acc2[0][2*u+1] = ffma2(xr0, w.y, acc2[0][2*u+1]);
                acc2[1][2*u]   = ffma2(xr1, w.x, acc2[1][2*u]);
                acc2[1][2*u+1] = ffma2(xr1, w.y, acc2[1][2*u+1]);
            }
        }
        __syncthreads();
    }
    #pragma unroll
    for (int r = 0; r < 2; r++)
        #pragma unroll
        for (int u = 0; u < 2; u++) {
            float v0, v1, v2, v3;
            unpack2(acc2[r][2*u], v0, v1); unpack2(acc2[r][2*u+1], v2, v3);
            float4 z = make_float4(fmaxf(v0, 0.f), fmaxf(v1, 0.f),
                                   fmaxf(v2, 0.f), fmaxf(v3, 0.f));
            *(float4*)&sX[(r0 + r) * 132 + jb2 + u * 32] = z;
        }
    __syncthreads();

    {
        int row = tid >> 3, seg = tid & 7;
        float p = 0.f;
        #pragma unroll
        for (int k = seg * 16; k < seg * 16 + 16; k++)
            p += sX[row * 132 + k] * sW3[k];
        #pragma unroll
        for (int o = 4; o > 0; o >>= 1)
            p += __shfl_down_sync(0xFFFFFFFFu, p, o, 8);
        if (seg == 0) out[b0 + row] = p + mb3[0];
    }
}

// ---------------------------------------------------------------------------
extern "C" void kernel_launch(void* const* d_in, const int* in_sizes, int n_in,
                              void* d_out, int out_size) {
    const int*   customer_id  = (const int*)d_in[0];
    const int*   cand_good    = (const int*)d_in[1];
    const int*   cand_class   = (const int*)d_in[2];
    const int*   hist_goods   = (const int*)d_in[3];
    const int*   hist_classes = (const int*)d_in[4];
    const float* user_table   = (const float*)d_in[5];
    const float* item_table   = (const float*)d_in[6];
    const float* cat_table    = (const float*)d_in[7];
    const float* aw1 = (const float*)d_in[8];
    const float* ab1 = (const float*)d_in[9];
    const float* aw2 = (const float*)d_in[10];
    const float* ab2 = (const float*)d_in[11];
    const float* mw1 = (const float*)d_in[12];
    const float* mb1 = (const float*)d_in[13];
    const float* mw2 = (const float*)d_in[14];
    const float* mb2 = (const float*)d_in[15];
    const float* mw3 = (const float*)d_in[16];
    const float* mb3 = (const float*)d_in[17];

    const int smemA = 28272 * 4;   // 113088 B
    const int smemB = 17856 * 4;
    cudaFuncSetAttribute(din_attention_kernel,
                         cudaFuncAttributeMaxDynamicSharedMemorySize, smemA);
    cudaFuncSetAttribute(din_mlp_kernel,
                         cudaFuncAttributeMaxDynamicSharedMemorySize, smemB);

    din_prep<<<20, 256>>>(aw1, aw2);

    din_attention_kernel<<<NB / GA, 256, smemA>>>(
        customer_id, cand_good, cand_class, hist_goods, hist_classes,
        user_table, item_table, cat_table, ab1, ab2);

    din_mlp_kernel<<<NB / 32, 256, smemB>>>(
        mw1, mb1, mw2, mb2, mw3, mb3, (float*)d_out);
}

// round 13
// speedup vs baseline: 2.1178x; 1.0883x over previous
#include <cuda_runtime.h>
#include <math.h>

#define GA 8
#define NB 16384

__device__ float g_comb[NB * 160];
__device__ uint2 g_Pb[2560];     // bf16 B-frag pairs: [32 frag-rows][80 n]
__device__ float g_AC[5120];     // A+C, [64 k][80 j]
__device__ float g_W2[80];

__device__ __forceinline__ unsigned long long pack2(float a, float b) {
    unsigned long long r;
    asm("mov.b64 %0, {%1, %2};" : "=l"(r) : "f"(a), "f"(b));
    return r;
}
__device__ __forceinline__ unsigned long long ffma2(unsigned long long a,
                                                    unsigned long long b,
                                                    unsigned long long c) {
    unsigned long long d;
    asm("fma.rn.f32x2 %0, %1, %2, %3;" : "=l"(d) : "l"(a), "l"(b), "l"(c));
    return d;
}
__device__ __forceinline__ void unpack2(unsigned long long v, float& a, float& b) {
    asm("mov.b64 {%0, %1}, %2;" : "=f"(a), "=f"(b) : "l"(v));
}
__device__ __forceinline__ unsigned pack_bf16x2(float lo, float hi) {
    unsigned r;   // low 16 bits <- lo, high 16 <- hi
    asm("cvt.rn.bf16x2.f32 %0, %1, %2;" : "=r"(r) : "f"(hi), "f"(lo));
    return r;
}
__device__ __forceinline__ void mma_bf16(float* c,
                                         unsigned a0, unsigned a1, unsigned a2, unsigned a3,
                                         unsigned b0, unsigned b1) {
    asm volatile("mma.sync.aligned.m16n8k16.row.col.f32.bf16.bf16.f32 "
                 "{%0,%1,%2,%3}, {%4,%5,%6,%7}, {%8,%9}, {%0,%1,%2,%3};"
                 : "+f"(c[0]), "+f"(c[1]), "+f"(c[2]), "+f"(c[3])
                 : "r"(a0), "r"(a1), "r"(a2), "r"(a3), "r"(b0), "r"(b1));
}
__device__ __forceinline__ void cp_async16(float* smem_dst, const float* gsrc) {
    unsigned s = (unsigned)__cvta_generic_to_shared(smem_dst);
    asm volatile("cp.async.cg.shared.global [%0], [%1], 16;" :: "r"(s), "l"(gsrc));
}
__device__ __forceinline__ void cp_async_commit() {
    asm volatile("cp.async.commit_group;");
}
__device__ __forceinline__ void cp_async_wait_all() {
    asm volatile("cp.async.wait_group 0;" ::: "memory");
}
__device__ __forceinline__ void bar_grp(int id) {
    asm volatile("bar.sync %0, %1;" :: "r"(id), "r"(128) : "memory");
}

// ---------------------------------------------------------------------------
// Prep: pack W=[B-C;E] (128k x 80n) into bf16 m16n8k16 B-fragments.
// Frag-row r = ks*4+tig (ks=0..7, K chunk of 16): pairs (k0,k0+1),(k0+8,k0+9)
// with k0 = ks*16 + tig*2.  Also AC = A+C and aw2 copy.
// ---------------------------------------------------------------------------
__global__ void din_prep(const float* __restrict__ aw1,
                         const float* __restrict__ aw2) {
    int idx = blockIdx.x * 256 + threadIdx.x;
    if (idx < 2560) {
        int r = idx / 80, n = idx - r * 80;
        int ks = r >> 2, tg = r & 3;
        int k0 = ks * 16 + tg * 2;
        float w[4];
        #pragma unroll
        for (int t = 0; t < 4; t++) {
            int kk = k0 + (t >> 1) * 8 + (t & 1);
            w[t] = (kk < 64)
                 ? aw1[(64 + kk) * 80 + n] - aw1[(128 + kk) * 80 + n]
                 : aw1[(192 + kk - 64) * 80 + n];
        }
        g_Pb[idx] = make_uint2(pack_bf16x2(w[0], w[1]), pack_bf16x2(w[2], w[3]));
    }
    if (idx < 5120) {
        int k = idx / 80, j = idx - k * 80;
        g_AC[idx] = aw1[k * 80 + j] + aw1[(128 + k) * 80 + j];
    }
    if (idx < 80) g_W2[idx] = aw2[idx];
}

// ---------------------------------------------------------------------------
// Attention: bf16 mma.m16n8k16, warp-per-m16-tile x all n=80, two independent
// 128-thread groups. smem 22352 floats = 89408 B, 2 CTAs/SM.
//  sPb 5376 | sH 4x3808 | sQ 512 | sR 640 | sW2 80 | sScore 128 | sWt 128
//  sPool 256
// ---------------------------------------------------------------------------
__global__ __launch_bounds__(256, 2)
void din_attention_kernel(
    const int* __restrict__ customer_id,
    const int* __restrict__ cand_good,
    const int* __restrict__ cand_class,
    const int* __restrict__ hist_goods,
    const int* __restrict__ hist_classes,
    const float* __restrict__ user_table,
    const float* __restrict__ item_table,
    const float* __restrict__ cat_table,
    const float* __restrict__ ab1,
    const float* __restrict__ ab2)
{
    extern __shared__ float sm[];
    uint2* sPb    = (uint2*)sm;        // 32 rows x 84 uint2 (5376 words)
    float* sH     = sm + 5376;         // 4 x 3808
    float* sQ     = sm + 20608;        // 512
    float* sR     = sm + 21120;        // 640 (stride 80)
    float* sW2    = sm + 21760;        // 80
    float* sScore = sm + 21840;        // 2 x 64
    float* sWt    = sm + 21968;        // 2 x 64
    float* sPool  = sm + 22096;        // 2 x 128

    const int tid  = threadIdx.x;
    const int warp = tid >> 5;
    const int lane = tid & 31;
    const int gid  = lane >> 2;        // 0..7
    const int tig  = lane & 3;         // 0..3
    const int grp  = warp >> 2;        // 0 or 1
    const int mt   = warp & 3;         // m16 tile
    const int tg128 = tid & 127;
    const int b0   = blockIdx.x * GA;
    const float ab2v = __ldg(ab2);

    // ================= Phase A (CTA-wide, once) =========================
    for (int idx = tid; idx < GA * 64; idx += 256) {
        int g = idx >> 6, d = idx & 63;
        int b = b0 + g;
        float v = (d < 32) ? item_table[cand_good[b] * 32 + d]
                           : cat_table[cand_class[b] * 32 + (d - 32)];
        sQ[idx] = v;
        g_comb[b * 160 + 32 + d] = v;
    }
    for (int idx = tid; idx < GA * 32; idx += 256) {
        int g = idx >> 5, d = idx & 31;
        int b = b0 + g;
        g_comb[b * 160 + d] = user_table[customer_id[b] * 32 + d];
    }
    // stage AC into sH region (stride 80)
    float* sAC = sH;
    #pragma unroll
    for (int i = 0; i < 5; i++) {
        int f4 = tid + 256 * i;   // 1280 float4
        *(float4*)&sAC[f4 * 4] = __ldg((const float4*)g_AC + f4);
    }
    if (tid < 80) sW2[tid] = g_W2[tid];
    // stage packed bf16 B-frags: 2560 uint2 = 1280 uint4 (40 uint4 per row,
    // smem row stride 42 uint4)   [fixes R11 bug: all 1280 copied]
    #pragma unroll
    for (int i = 0; i < 5; i++) {
        int v = tid + 256 * i;    // 1280 uint4
        int row = v / 40, n2 = v - row * 40;
        ((uint4*)sm)[row * 42 + n2] = __ldg((const uint4*)g_Pb + v);
    }
    __syncthreads();
    // r[g][j] = ab1[j] + sum_k q[g][k]*AC[k][j]
    for (int idx = tid; idx < 640; idx += 256) {
        int g = idx / 80, j = idx - g * 80;
        float v = __ldg(&ab1[j]);
        #pragma unroll 8
        for (int k = 0; k < 64; k++)
            v += sQ[g * 64 + k] * sAC[k * 80 + j];
        sR[idx] = v;
    }
    __syncthreads();   // sPb, sR ready; sAC region free for H buffers

    // ================= Phase B (two independent groups) =================
    const int barid = grp + 1;
    float* bufA = sH + (grp * 2) * 3808;
    float* bufB = sH + (grp * 2 + 1) * 3808;
    const int gfirst = grp * 4;

    {
        const int b = b0 + gfirst;
        for (int f4 = tg128; f4 < 800; f4 += 128) {
            int l = f4 >> 4, q4 = f4 & 15, d0 = q4 * 4;
            const float* src;
            if (d0 < 32) src = item_table + hist_goods[b * 50 + l] * 32 + d0;
            else         src = cat_table  + hist_classes[b * 50 + l] * 32 + (d0 - 32);
            cp_async16(&bufA[l * 68 + d0], src);
        }
        cp_async_commit();
        cp_async_wait_all();
        bar_grp(barid);
    }

    const int r_lo = mt * 16 + gid;
    const int r_hi = r_lo + 8;

    for (int i = 0; i < 4; i++) {
        const int gg = gfirst + i;
        const int b  = b0 + gg;
        float* Hc = (i & 1) ? bufB : bufA;
        float* Ha = (i & 1) ? bufA : bufB;

        if (i < 3) {
            const int bn = b + 1;
            for (int f4 = tg128; f4 < 800; f4 += 128) {
                int l = f4 >> 4, q4 = f4 & 15, d0 = q4 * 4;
                const float* src;
                if (d0 < 32) src = item_table + hist_goods[bn * 50 + l] * 32 + d0;
                else         src = cat_table  + hist_classes[bn * 50 + l] * 32 + (d0 - 32);
                cp_async16(&Ha[l * 68 + d0], src);
            }
            cp_async_commit();
        }
        int mk0 = 1, mk1 = 1;
        if (tig == 0) {
            if (r_lo < 50) mk0 = hist_goods[b * 50 + r_lo];
            if (r_hi < 50) mk1 = hist_goods[b * 50 + r_hi];
        }

        // ---- bf16 MMA: rows [mt*16, +16), all n=80, K=128 (8 chunks) ----
        float acc[10][4];
        #pragma unroll
        for (int nt = 0; nt < 10; nt++)
            acc[nt][0] = acc[nt][1] = acc[nt][2] = acc[nt][3] = 0.f;

        #pragma unroll
        for (int ks = 0; ks < 8; ks++) {
            unsigned a0, a1, a2, a3;
            if (ks < 4) {
                const int c = ks * 16 + tig * 2;
                float2 x0 = *(const float2*)&Hc[r_lo * 68 + c];
                float2 x1 = *(const float2*)&Hc[r_hi * 68 + c];
                float2 x2 = *(const float2*)&Hc[r_lo * 68 + c + 8];
                float2 x3 = *(const float2*)&Hc[r_hi * 68 + c + 8];
                a0 = pack_bf16x2(x0.x, x0.y);
                a1 = pack_bf16x2(x1.x, x1.y);
                a2 = pack_bf16x2(x2.x, x2.y);
                a3 = pack_bf16x2(x3.x, x3.y);
            } else {
                const int c = (ks - 4) * 16 + tig * 2;
                float2 x0 = *(const float2*)&Hc[r_lo * 68 + c];
                float2 x1 = *(const float2*)&Hc[r_hi * 68 + c];
                float2 x2 = *(const float2*)&Hc[r_lo * 68 + c + 8];
                float2 x3 = *(const float2*)&Hc[r_hi * 68 + c + 8];
                float2 ql = *(const float2*)&sQ[gg * 64 + c];
                float2 qh = *(const float2*)&sQ[gg * 64 + c + 8];
                a0 = pack_bf16x2(x0.x * ql.x, x0.y * ql.y);
                a1 = pack_bf16x2(x1.x * ql.x, x1.y * ql.y);
                a2 = pack_bf16x2(x2.x * qh.x, x2.y * qh.y);
                a3 = pack_bf16x2(x3.x * qh.x, x3.y * qh.y);
            }
            const uint2* P = sPb + (ks * 4 + tig) * 84;
            #pragma unroll
            for (int nt = 0; nt < 10; nt++) {
                uint2 bb = P[nt * 8 + gid];
                mma_bf16(acc[nt], a0, a1, a2, a3, bb.x, bb.y);
            }
        }

        // ---- epilogue: score = relu(S + r) . w2, reduce over tig ---------
        float slo = 0.f, shi = 0.f;
        #pragma unroll
        for (int nt = 0; nt < 10; nt++) {
            const int j0 = nt * 8 + tig * 2;
            float r0v = sR[gg * 80 + j0], r1v = sR[gg * 80 + j0 + 1];
            float w0 = sW2[j0], w1 = sW2[j0 + 1];
            slo += fmaxf(acc[nt][0] + r0v, 0.f) * w0
                 + fmaxf(acc[nt][1] + r1v, 0.f) * w1;
            shi += fmaxf(acc[nt][2] + r0v, 0.f) * w0
                 + fmaxf(acc[nt][3] + r1v, 0.f) * w1;
        }
        slo += __shfl_down_sync(0xFFFFFFFFu, slo, 2, 4);
        slo += __shfl_down_sync(0xFFFFFFFFu, slo, 1, 4);
        shi += __shfl_down_sync(0xFFFFFFFFu, shi, 2, 4);
        shi += __shfl_down_sync(0xFFFFFFFFu, shi, 1, 4);
        if (tig == 0) {
            if (r_lo < 50)
                sScore[grp * 64 + r_lo] = (mk0 == 0) ? -1e9f : slo + ab2v;
            if (r_hi < 50)
                sScore[grp * 64 + r_hi] = (mk1 == 0) ? -1e9f : shi + ab2v;
        }
        bar_grp(barid);   // bar1: scores ready

        if (mt == 0) {
            float s0 = (lane < 50) ? sScore[grp * 64 + lane] : -INFINITY;
            float s1 = (lane + 32 < 50) ? sScore[grp * 64 + lane + 32] : -INFINITY;
            float mx = fmaxf(s0, s1);
            #pragma unroll
            for (int o = 16; o > 0; o >>= 1)
                mx = fmaxf(mx, __shfl_xor_sync(0xFFFFFFFFu, mx, o));
            float e0 = (lane < 50) ? expf(s0 - mx) : 0.f;
            float e1 = (lane + 32 < 50) ? expf(s1 - mx) : 0.f;
            float sum = e0 + e1;
            #pragma unroll
            for (int o = 16; o > 0; o >>= 1)
                sum += __shfl_xor_sync(0xFFFFFFFFu, sum, o);
            float inv = 1.f / sum;
            if (lane < 50) sWt[grp * 64 + lane] = e0 * inv;
            if (lane + 32 < 50) sWt[grp * 64 + lane + 32] = e1 * inv;
        }
        bar_grp(barid);   // bar2: weights ready

        {
            int d = tg128 & 63, lh = tg128 >> 6;
            int l0 = lh * 25;
            float p = 0.f;
            #pragma unroll 5
            for (int l = l0; l < l0 + 25; l++)
                p += sWt[grp * 64 + l] * Hc[l * 68 + d];
            sPool[grp * 128 + tg128] = p;
        }
        if (i < 3) cp_async_wait_all();
        bar_grp(barid);   // bar3: pool partials + next H ready
        if (tg128 < 64)
            g_comb[b * 160 + 96 + tg128] =
                sPool[grp * 128 + tg128] + sPool[grp * 128 + 64 + tg128];
    }
}

// ---------------------------------------------------------------------------
// MLP 160 -> 256 -> 128 -> 1 (unchanged). 32 rows/CTA, 3 CTAs/SM.
// ---------------------------------------------------------------------------
__global__ __launch_bounds__(256, 3)
void din_mlp_kernel(const float* __restrict__ mw1, const float* __restrict__ mb1,
                    const float* __restrict__ mw2, const float* __restrict__ mb2,
                    const float* __restrict__ mw3, const float* __restrict__ mb3,
                    float* __restrict__ out)
{
    extern __shared__ float sm[];
    float* sX  = sm;            // 5248
    float* sW  = sm + 5248;     // 4160
    float* sZ1 = sm + 9408;     // 8320
    float* sW3 = sm + 17728;    // 128

    const int tid = threadIdx.x;
    const int b0  = blockIdx.x * 32;

    for (int f = tid; f < 1280; f += 256) {
        int row = f / 40, c4 = f - row * 40;
        *(float4*)&sX[row * 164 + c4 * 4] =
            *(const float4*)&g_comb[(b0 + row) * 160 + c4 * 4];
    }
    if (tid < 128) sW3[tid] = mw3[tid];

    const int half = tid >> 7;
    const int t    = tid & 127;
    const int rp   = t >> 3;
    const int c0   = t & 7;
    const int r0   = rp * 2;
    const int jb1  = half * 128 + c0 * 4;
    const int jb2  = half * 64  + c0 * 4;

    unsigned long long acc1[2][8];
    #pragma unroll
    for (int u = 0; u < 4; u++) {
        ulonglong2 bb = *(const ulonglong2*)&mb1[jb1 + u * 32];
        acc1[0][2*u] = bb.x; acc1[0][2*u+1] = bb.y;
        acc1[1][2*u] = bb.x; acc1[1][2*u+1] = bb.y;
    }
    float4 pf[4];
    #pragma unroll
    for (int i = 0; i < 4; i++)
        pf[i] = *(const float4*)&mw1[tid * 4 + i * 1024];

    for (int s = 0; s < 10; s++) {
        #pragma unroll
        for (int i = 0; i < 4; i++) {
            int o = tid * 4 + i * 1024;
            *(float4*)&sW[(o >> 8) * 260 + (o & 255)] = pf[i];
        }
        __syncthreads();
        if (s < 9) {
            const float* src = mw1 + (s + 1) * 4096;
            #pragma unroll
            for (int i = 0; i < 4; i++)
                pf[i] = *(const float4*)&src[tid * 4 + i * 1024];
        }
        const int xb = s * 16;
        #pragma unroll 4
        for (int kk = 0; kk < 16; kk++) {
            float x0 = sX[r0 * 164 + xb + kk];
            float x1 = sX[(r0 + 1) * 164 + xb + kk];
            unsigned long long xr0 = pack2(x0, x0);
            unsigned long long xr1 = pack2(x1, x1);
            #pragma unroll
            for (int u = 0; u < 4; u++) {
                ulonglong2 w = *(const ulonglong2*)&sW[kk * 260 + jb1 + u * 32];
                acc1[0][2*u]   = ffma2(xr0, w.x, acc1[0][2*u]);
                acc1[0][2*u+1] = ffma2(xr0, w.y, acc1[0][2*u+1]);
                acc1[1][2*u]   = ffma2(xr1, w.x, acc1[1][2*u]);
                acc1[1][2*u+1] = ffma2(xr1, w.y, acc1[1][2*u+1]);
            }
        }
        __syncthreads();
    }
    #pragma unroll
    for (int r = 0; r < 2; r++)
        #pragma unroll
        for (int u = 0; u < 4; u++) {
            float v0, v1, v2, v3;
            unpack2(acc1[r][2*u], v0, v1); unpack2(acc1[r][2*u+1], v2, v3);
            float4 z = make_float4(fmaxf(v0, 0.f), fmaxf(v1, 0.f),
                                   fmaxf(v2, 0.f), fmaxf(v3, 0.f));
            *(float4*)&sZ1[(r0 + r) * 260 + jb1 + u * 32] = z;
        }

    unsigned long long acc2[2][4];
    #pragma unroll
    for (int u = 0; u < 2; u++) {
        ulonglong2 bb = *(const ulonglong2*)&mb2[jb2 + u * 32];
        acc2[0][2*u] = bb.x; acc2[0][2*u+1] = bb.y;
        acc2[1][2*u] = bb.x; acc2[1][2*u+1] = bb.y;
    }
    float4 pg[2];
    #pragma unroll
    for (int i = 0; i < 2; i++)
        pg[i] = *(const float4*)&mw2[tid * 4 + i * 1024];

    for (int s = 0; s < 16; s++) {
        #pragma unroll
        for (int i = 0; i < 2; i++) {
            int o = tid * 4 + i * 1024;
            *(float4*)&sW[(o >> 7) * 132 + (o & 127)] = pg[i];
        }
        __syncthreads();
        if (s < 15) {
            const float* src = mw2 + (s + 1) * 2048;
            #pragma unroll
            for (int i = 0; i < 2; i++)
                pg[i] = *(const float4*)&src[tid * 4 + i * 1024];
        }
        const int xb = s * 16;
        #pragma unroll 4
        for (int kk = 0; kk < 16; kk++) {
            float x0 = sZ1[r0 * 260 + xb + kk];
            float x1 = sZ1[(r0 + 1) * 260 + xb + kk];
            unsigned long long xr0 = pack2(x0, x0);
            unsigned long long xr1 = pack2(x1, x1);
            #pragma unroll
            for (int u = 0; u < 2; u++) {
                ulonglong2 w = *(const ulonglong2*)&sW[kk * 132 + jb2 + u * 32];
                acc2[0][2*u]   = ffma2(xr0, w.x, acc2[0][2*u]);
                acc2[0][2*u+1] = ffma2(xr0, w.y, acc2[0][2*u+1]);
                acc2[1][2*u]   = ffma2(xr1, w.x, acc2[1][2*u]);
                acc2[1][2*u+1] = ffma2(xr1, w.y, acc2[1][2*u+1]);
            }
        }
        __syncthreads();
    }
    #pragma unroll
    for (int r = 0; r < 2; r++)
        #pragma unroll
        for (int u = 0; u < 2; u++) {
            float v0, v1, v2, v3;
            unpack2(acc2[r][2*u], v0, v1); unpack2(acc2[r][2*u+1], v2, v3);
            float4 z = make_float4(fmaxf(v0, 0.f), fmaxf(v1, 0.f),
                                   fmaxf(v2, 0.f), fmaxf(v3, 0.f));
            *(float4*)&sX[(r0 + r) * 132 + jb2 + u * 32] = z;
        }
    __syncthreads();

    {
        int row = tid >> 3, seg = tid & 7;
        float p = 0.f;
        #pragma unroll
        for (int k = seg * 16; k < seg * 16 + 16; k++)
            p += sX[row * 132 + k] * sW3[k];
        #pragma unroll
        for (int o = 4; o > 0; o >>= 1)
            p += __shfl_down_sync(0xFFFFFFFFu, p, o, 8);
        if (seg == 0) out[b0 + row] = p + mb3[0];
    }
}

// ---------------------------------------------------------------------------
extern "C" void kernel_launch(void* const* d_in, const int* in_sizes, int n_in,
                              void* d_out, int out_size) {
    const int*   customer_id  = (const int*)d_in[0];
    const int*   cand_good    = (const int*)d_in[1];
    const int*   cand_class   = (const int*)d_in[2];
    const int*   hist_goods   = (const int*)d_in[3];
    const int*   hist_classes = (const int*)d_in[4];
    const float* user_table   = (const float*)d_in[5];
    const float* item_table   = (const float*)d_in[6];
    const float* cat_table    = (const float*)d_in[7];
    const float* aw1 = (const float*)d_in[8];
    const float* ab1 = (const float*)d_in[9];
    const float* aw2 = (const float*)d_in[10];
    const float* ab2 = (const float*)d_in[11];
    const float* mw1 = (const float*)d_in[12];
    const float* mb1 = (const float*)d_in[13];
    const float* mw2 = (const float*)d_in[14];
    const float* mb2 = (const float*)d_in[15];
    const float* mw3 = (const float*)d_in[16];
    const float* mb3 = (const float*)d_in[17];

    const int smemA = 22352 * 4;   // 89408 B
    const int smemB = 17856 * 4;
    cudaFuncSetAttribute(din_attention_kernel,
                         cudaFuncAttributeMaxDynamicSharedMemorySize, smemA);
    cudaFuncSetAttribute(din_mlp_kernel,
                         cudaFuncAttributeMaxDynamicSharedMemorySize, smemB);

    din_prep<<<20, 256>>>(aw1, aw2);

    din_attention_kernel<<<NB / GA, 256, smemA>>>(
        customer_id, cand_good, cand_class, hist_goods, hist_classes,
        user_table, item_table, cat_table, ab1, ab2);

    din_mlp_kernel<<<NB / 32, 256, smemB>>>(
        mw1, mb1, mw2, mb2, mw3, mb3, (float*)d_out);
}

// round 15
// speedup vs baseline: 2.9306x; 1.3838x over previous
#include <cuda_runtime.h>
#include <math.h>

#define GA 8
#define NB 16384

__device__ float g_comb[NB * 160];
__device__ uint2 g_Pb[2560];      // attention W frags  [32 rows][80 n]
__device__ float g_AC[5120];      // A+C, [64 k][80 j]
__device__ float g_W2[80];
__device__ uint2 g_P1h[10240];    // mlp L1 W frags hi  [40 rows][256 n]
__device__ uint2 g_P1l[10240];    //                lo
__device__ uint2 g_P2h[8192];     // mlp L2 W frags hi  [64 rows][128 n]
__device__ uint2 g_P2l[8192];     //                lo

__device__ __forceinline__ unsigned pack_bf16x2(float lo, float hi) {
    unsigned r;   // low 16 bits <- lo, high 16 <- hi
    asm("cvt.rn.bf16x2.f32 %0, %1, %2;" : "=r"(r) : "f"(hi), "f"(lo));
    return r;
}
__device__ __forceinline__ float bflo(unsigned p) {
    return __uint_as_float(p << 16);
}
__device__ __forceinline__ float bfhi(unsigned p) {
    return __uint_as_float(p & 0xFFFF0000u);
}
__device__ __forceinline__ void mma_bf16(float* c,
                                         unsigned a0, unsigned a1, unsigned a2, unsigned a3,
                                         unsigned b0, unsigned b1) {
    asm volatile("mma.sync.aligned.m16n8k16.row.col.f32.bf16.bf16.f32 "
                 "{%0,%1,%2,%3}, {%4,%5,%6,%7}, {%8,%9}, {%0,%1,%2,%3};"
                 : "+f"(c[0]), "+f"(c[1]), "+f"(c[2]), "+f"(c[3])
                 : "r"(a0), "r"(a1), "r"(a2), "r"(a3), "r"(b0), "r"(b1));
}
__device__ __forceinline__ void cp_async16(float* smem_dst, const float* gsrc) {
    unsigned s = (unsigned)__cvta_generic_to_shared(smem_dst);
    asm volatile("cp.async.cg.shared.global [%0], [%1], 16;" :: "r"(s), "l"(gsrc));
}
__device__ __forceinline__ void cp_async_commit() {
    asm volatile("cp.async.commit_group;");
}
__device__ __forceinline__ void cp_async_wait_all() {
    asm volatile("cp.async.wait_group 0;" ::: "memory");
}
__device__ __forceinline__ void bar_grp(int id) {
    asm volatile("bar.sync %0, %1;" :: "r"(id), "r"(128) : "memory");
}

// ---------------------------------------------------------------------------
// Prep: attention W frags (as R13) + AC + aw2, and MLP split-bf16 W frags.
// bf16 B-frag row r = ks*4+tig: pairs (k0,k0+1),(k0+8,k0+9), k0=ks*16+tig*2.
// ---------------------------------------------------------------------------
__global__ void din_prep(const float* __restrict__ aw1,
                         const float* __restrict__ aw2,
                         const float* __restrict__ mw1,
                         const float* __restrict__ mw2) {
    int idx = blockIdx.x * 256 + threadIdx.x;
    if (idx < 2560) {
        int r = idx / 80, n = idx - r * 80;
        int ks = r >> 2, tg = r & 3;
        int k0 = ks * 16 + tg * 2;
        float w[4];
        #pragma unroll
        for (int t = 0; t < 4; t++) {
            int kk = k0 + (t >> 1) * 8 + (t & 1);
            w[t] = (kk < 64)
                 ? aw1[(64 + kk) * 80 + n] - aw1[(128 + kk) * 80 + n]
                 : aw1[(192 + kk - 64) * 80 + n];
        }
        g_Pb[idx] = make_uint2(pack_bf16x2(w[0], w[1]), pack_bf16x2(w[2], w[3]));
    }
    if (idx < 5120) {
        int k = idx / 80, j = idx - k * 80;
        g_AC[idx] = aw1[k * 80 + j] + aw1[(128 + k) * 80 + j];
    }
    if (idx < 80) g_W2[idx] = aw2[idx];
    if (idx < 10240) {       // layer1 W frags, split hi/lo
        int r = idx >> 8, n = idx & 255;
        int k0 = (r >> 2) * 16 + (r & 3) * 2;
        float w0 = mw1[k0 * 256 + n],      w1 = mw1[(k0 + 1) * 256 + n];
        float w2 = mw1[(k0 + 8) * 256 + n], w3 = mw1[(k0 + 9) * 256 + n];
        unsigned h0 = pack_bf16x2(w0, w1), h1 = pack_bf16x2(w2, w3);
        unsigned l0 = pack_bf16x2(w0 - bflo(h0), w1 - bfhi(h0));
        unsigned l1 = pack_bf16x2(w2 - bflo(h1), w3 - bfhi(h1));
        g_P1h[idx] = make_uint2(h0, h1);
        g_P1l[idx] = make_uint2(l0, l1);
    }
    if (idx < 8192) {        // layer2 W frags, split hi/lo
        int r = idx >> 7, n = idx & 127;
        int k0 = (r >> 2) * 16 + (r & 3) * 2;
        float w0 = mw2[k0 * 128 + n],      w1 = mw2[(k0 + 1) * 128 + n];
        float w2 = mw2[(k0 + 8) * 128 + n], w3 = mw2[(k0 + 9) * 128 + n];
        unsigned h0 = pack_bf16x2(w0, w1), h1 = pack_bf16x2(w2, w3);
        unsigned l0 = pack_bf16x2(w0 - bflo(h0), w1 - bfhi(h0));
        unsigned l1 = pack_bf16x2(w2 - bflo(h1), w3 - bfhi(h1));
        g_P2h[idx] = make_uint2(h0, h1);
        g_P2l[idx] = make_uint2(l0, l1);
    }
}

// ---------------------------------------------------------------------------
// Attention: bf16 mma (UNCHANGED from R13-pass). 89408 B smem, 2 CTAs/SM.
// ---------------------------------------------------------------------------
__global__ __launch_bounds__(256, 2)
void din_attention_kernel(
    const int* __restrict__ customer_id,
    const int* __restrict__ cand_good,
    const int* __restrict__ cand_class,
    const int* __restrict__ hist_goods,
    const int* __restrict__ hist_classes,
    const float* __restrict__ user_table,
    const float* __restrict__ item_table,
    const float* __restrict__ cat_table,
    const float* __restrict__ ab1,
    const float* __restrict__ ab2)
{
    extern __shared__ float sm[];
    uint2* sPb    = (uint2*)sm;        // 32 rows x 84 uint2
    float* sH     = sm + 5376;         // 4 x 3808
    float* sQ     = sm + 20608;
    float* sR     = sm + 21120;
    float* sW2    = sm + 21760;
    float* sScore = sm + 21840;
    float* sWt    = sm + 21968;
    float* sPool  = sm + 22096;

    const int tid  = threadIdx.x;
    const int warp = tid >> 5;
    const int lane = tid & 31;
    const int gid  = lane >> 2;
    const int tig  = lane & 3;
    const int grp  = warp >> 2;
    const int mt   = warp & 3;
    const int tg128 = tid & 127;
    const int b0   = blockIdx.x * GA;
    const float ab2v = __ldg(ab2);

    for (int idx = tid; idx < GA * 64; idx += 256) {
        int g = idx >> 6, d = idx & 63;
        int b = b0 + g;
        float v = (d < 32) ? item_table[cand_good[b] * 32 + d]
                           : cat_table[cand_class[b] * 32 + (d - 32)];
        sQ[idx] = v;
        g_comb[b * 160 + 32 + d] = v;
    }
    for (int idx = tid; idx < GA * 32; idx += 256) {
        int g = idx >> 5, d = idx & 31;
        int b = b0 + g;
        g_comb[b * 160 + d] = user_table[customer_id[b] * 32 + d];
    }
    float* sAC = sH;
    #pragma unroll
    for (int i = 0; i < 5; i++) {
        int f4 = tid + 256 * i;
        *(float4*)&sAC[f4 * 4] = __ldg((const float4*)g_AC + f4);
    }
    if (tid < 80) sW2[tid] = g_W2[tid];
    #pragma unroll
    for (int i = 0; i < 5; i++) {
        int v = tid + 256 * i;
        int row = v / 40, n2 = v - row * 40;
        ((uint4*)sm)[row * 42 + n2] = __ldg((const uint4*)g_Pb + v);
    }
    __syncthreads();
    for (int idx = tid; idx < 640; idx += 256) {
        int g = idx / 80, j = idx - g * 80;
        float v = __ldg(&ab1[j]);
        #pragma unroll 8
        for (int k = 0; k < 64; k++)
            v += sQ[g * 64 + k] * sAC[k * 80 + j];
        sR[idx] = v;
    }
    __syncthreads();

    const int barid = grp + 1;
    float* bufA = sH + (grp * 2) * 3808;
    float* bufB = sH + (grp * 2 + 1) * 3808;
    const int gfirst = grp * 4;

    {
        const int b = b0 + gfirst;
        for (int f4 = tg128; f4 < 800; f4 += 128) {
            int l = f4 >> 4, q4 = f4 & 15, d0 = q4 * 4;
            const float* src;
            if (d0 < 32) src = item_table + hist_goods[b * 50 + l] * 32 + d0;
            else         src = cat_table  + hist_classes[b * 50 + l] * 32 + (d0 - 32);
            cp_async16(&bufA[l * 68 + d0], src);
        }
        cp_async_commit();
        cp_async_wait_all();
        bar_grp(barid);
    }

    const int r_lo = mt * 16 + gid;
    const int r_hi = r_lo + 8;

    for (int i = 0; i < 4; i++) {
        const int gg = gfirst + i;
        const int b  = b0 + gg;
        float* Hc = (i & 1) ? bufB : bufA;
        float* Ha = (i & 1) ? bufA : bufB;

        if (i < 3) {
            const int bn = b + 1;
            for (int f4 = tg128; f4 < 800; f4 += 128) {
                int l = f4 >> 4, q4 = f4 & 15, d0 = q4 * 4;
                const float* src;
                if (d0 < 32) src = item_table + hist_goods[bn * 50 + l] * 32 + d0;
                else         src = cat_table  + hist_classes[bn * 50 + l] * 32 + (d0 - 32);
                cp_async16(&Ha[l * 68 + d0], src);
            }
            cp_async_commit();
        }
        int mk0 = 1, mk1 = 1;
        if (tig == 0) {
            if (r_lo < 50) mk0 = hist_goods[b * 50 + r_lo];
            if (r_hi < 50) mk1 = hist_goods[b * 50 + r_hi];
        }

        float acc[10][4];
        #pragma unroll
        for (int nt = 0; nt < 10; nt++)
            acc[nt][0] = acc[nt][1] = acc[nt][2] = acc[nt][3] = 0.f;

        #pragma unroll
        for (int ks = 0; ks < 8; ks++) {
            unsigned a0, a1, a2, a3;
            if (ks < 4) {
                const int c = ks * 16 + tig * 2;
                float2 x0 = *(const float2*)&Hc[r_lo * 68 + c];
                float2 x1 = *(const float2*)&Hc[r_hi * 68 + c];
                float2 x2 = *(const float2*)&Hc[r_lo * 68 + c + 8];
                float2 x3 = *(const float2*)&Hc[r_hi * 68 + c + 8];
                a0 = pack_bf16x2(x0.x, x0.y);
                a1 = pack_bf16x2(x1.x, x1.y);
                a2 = pack_bf16x2(x2.x, x2.y);
                a3 = pack_bf16x2(x3.x, x3.y);
            } else {
                const int c = (ks - 4) * 16 + tig * 2;
                float2 x0 = *(const float2*)&Hc[r_lo * 68 + c];
                float2 x1 = *(const float2*)&Hc[r_hi * 68 + c];
                float2 x2 = *(const float2*)&Hc[r_lo * 68 + c + 8];
                float2 x3 = *(const float2*)&Hc[r_hi * 68 + c + 8];
                float2 ql = *(const float2*)&sQ[gg * 64 + c];
                float2 qh = *(const float2*)&sQ[gg * 64 + c + 8];
                a0 = pack_bf16x2(x0.x * ql.x, x0.y * ql.y);
                a1 = pack_bf16x2(x1.x * ql.x, x1.y * ql.y);
                a2 = pack_bf16x2(x2.x * qh.x, x2.y * qh.y);
                a3 = pack_bf16x2(x3.x * qh.x, x3.y * qh.y);
            }
            const uint2* P = sPb + (ks * 4 + tig) * 84;
            #pragma unroll
            for (int nt = 0; nt < 10; nt++) {
                uint2 bb = P[nt * 8 + gid];
                mma_bf16(acc[nt], a0, a1, a2, a3, bb.x, bb.y);
            }
        }

        float slo = 0.f, shi = 0.f;
        #pragma unroll
        for (int nt = 0; nt < 10; nt++) {
            const int j0 = nt * 8 + tig * 2;
            float r0v = sR[gg * 80 + j0], r1v = sR[gg * 80 + j0 + 1];
            float w0 = sW2[j0], w1 = sW2[j0 + 1];
            slo += fmaxf(acc[nt][0] + r0v, 0.f) * w0
                 + fmaxf(acc[nt][1] + r1v, 0.f) * w1;
            shi += fmaxf(acc[nt][2] + r0v, 0.f) * w0
                 + fmaxf(acc[nt][3] + r1v, 0.f) * w1;
        }
        slo += __shfl_down_sync(0xFFFFFFFFu, slo, 2, 4);
        slo += __shfl_down_sync(0xFFFFFFFFu, slo, 1, 4);
        shi += __shfl_down_sync(0xFFFFFFFFu, shi, 2, 4);
        shi += __shfl_down_sync(0xFFFFFFFFu, shi, 1, 4);
        if (tig == 0) {
            if (r_lo < 50)
                sScore[grp * 64 + r_lo] = (mk0 == 0) ? -1e9f : slo + ab2v;
            if (r_hi < 50)
                sScore[grp * 64 + r_hi] = (mk1 == 0) ? -1e9f : shi + ab2v;
        }
        bar_grp(barid);

        if (mt == 0) {
            float s0 = (lane < 50) ? sScore[grp * 64 + lane] : -INFINITY;
            float s1 = (lane + 32 < 50) ? sScore[grp * 64 + lane + 32] : -INFINITY;
            float mx = fmaxf(s0, s1);
            #pragma unroll
            for (int o = 16; o > 0; o >>= 1)
                mx = fmaxf(mx, __shfl_xor_sync(0xFFFFFFFFu, mx, o));
            float e0 = (lane < 50) ? expf(s0 - mx) : 0.f;
            float e1 = (lane + 32 < 50) ? expf(s1 - mx) : 0.f;
            float sum = e0 + e1;
            #pragma unroll
            for (int o = 16; o > 0; o >>= 1)
                sum += __shfl_xor_sync(0xFFFFFFFFu, sum, o);
            float inv = 1.f / sum;
            if (lane < 50) sWt[grp * 64 + lane] = e0 * inv;
            if (lane + 32 < 50) sWt[grp * 64 + lane + 32] = e1 * inv;
        }
        bar_grp(barid);

        {
            int d = tg128 & 63, lh = tg128 >> 6;
            int l0 = lh * 25;
            float p = 0.f;
            #pragma unroll 5
            for (int l = l0; l < l0 + 25; l++)
                p += sWt[grp * 64 + l] * Hc[l * 68 + d];
            sPool[grp * 128 + tg128] = p;
        }
        if (i < 3) cp_async_wait_all();
        bar_grp(barid);
        if (tg128 < 64)
            g_comb[b * 160 + 96 + tg128] =
                sPool[grp * 128 + tg128] + sPool[grp * 128 + 64 + tg128];
    }
}

// ---------------------------------------------------------------------------
// MLP v2: split-bf16 tensor-core 160->256->128->1. 32 rows/CTA, 512 CTAs,
// 256 thr, 3 CTAs/SM. smem 18176 floats = 72704 B:
//  sXh 2688 | sXl 2688 | sZ1h 4224 | sZ1l 4224 | sZ2 4224 | sW3 128
// Warp w: all 2 m-tiles x n-slice (L1: 32 cols, L2: 16 cols). 3 syncs total.
// ---------------------------------------------------------------------------
__global__ __launch_bounds__(256, 3)
void din_mlp_kernel(const float* __restrict__ mb1,
                    const float* __restrict__ mb2,
                    const float* __restrict__ mw3,
                    const float* __restrict__ mb3,
                    float* __restrict__ out)
{
    extern __shared__ float smf[];
    unsigned* sXh  = (unsigned*)smf;          // 32 x 84
    unsigned* sXl  = sXh + 2688;              // 32 x 84
    unsigned* sZ1h = sXl + 2688;              // 32 x 132
    unsigned* sZ1l = sZ1h + 4224;             // 32 x 132
    float*    sZ2  = (float*)(sZ1l + 4224);   // 32 x 132
    float*    sW3  = sZ2 + 4224;              // 128

    const int tid  = threadIdx.x;
    const int warp = tid >> 5;
    const int lane = tid & 31;
    const int gid  = lane >> 2;
    const int tig  = lane & 3;
    const int b0   = blockIdx.x * 32;

    // ---- load X and split to bf16 hi/lo (2560 float2) -------------------
    #pragma unroll
    for (int i = 0; i < 10; i++) {
        int v = tid + 256 * i;
        int row = v / 80, w = v - row * 80;
        float2 x = *(const float2*)&g_comb[(b0 + row) * 160 + w * 2];
        unsigned h = pack_bf16x2(x.x, x.y);
        unsigned l = pack_bf16x2(x.x - bflo(h), x.y - bfhi(h));
        sXh[row * 84 + w] = h;
        sXl[row * 84 + w] = l;
    }
    if (tid < 128) sW3[tid] = mw3[tid];
    __syncthreads();

    // ---- Layer 1: 160 -> 256 (10 k-chunks, warp n-slice = 32 cols) ------
    const int nb1 = warp * 32;
    float acc1[4][2][4];
    #pragma unroll
    for (int nt = 0; nt < 4; nt++)
        #pragma unroll
        for (int m = 0; m < 2; m++)
            acc1[nt][m][0] = acc1[nt][m][1] = acc1[nt][m][2] = acc1[nt][m][3] = 0.f;

    #pragma unroll
    for (int ks = 0; ks < 10; ks++) {
        unsigned ah[2][4], al[2][4];
        #pragma unroll
        for (int m = 0; m < 2; m++) {
            int rl = (m * 16 + gid) * 84, rh = rl + 8 * 84;
            int wi = ks * 8 + tig;
            ah[m][0] = sXh[rl + wi];     al[m][0] = sXl[rl + wi];
            ah[m][1] = sXh[rh + wi];     al[m][1] = sXl[rh + wi];
            ah[m][2] = sXh[rl + wi + 4]; al[m][2] = sXl[rl + wi + 4];
            ah[m][3] = sXh[rh + wi + 4]; al[m][3] = sXl[rh + wi + 4];
        }
        #pragma unroll
        for (int nt = 0; nt < 4; nt++) {
            int bi = (ks * 4 + tig) * 256 + nb1 + nt * 8 + gid;
            uint2 bh = __ldg(&g_P1h[bi]);
            uint2 bl = __ldg(&g_P1l[bi]);
            #pragma unroll
            for (int m = 0; m < 2; m++) {
                mma_bf16(acc1[nt][m], ah[m][0], ah[m][1], ah[m][2], ah[m][3], bh.x, bh.y);
                mma_bf16(acc1[nt][m], al[m][0], al[m][1], al[m][2], al[m][3], bh.x, bh.y);
                mma_bf16(acc1[nt][m], ah[m][0], ah[m][1], ah[m][2], ah[m][3], bl.x, bl.y);
            }
        }
    }
    // epilogue: relu(+bias), split-pack into sZ1h/sZ1l
    #pragma unroll
    for (int nt = 0; nt < 4; nt++) {
        int j0 = nb1 + nt * 8 + tig * 2;
        float b0v = __ldg(&mb1[j0]), b1v = __ldg(&mb1[j0 + 1]);
        int wx = (j0 >> 1);
        #pragma unroll
        for (int m = 0; m < 2; m++) {
            int rl = m * 16 + gid;
            float v0 = fmaxf(acc1[nt][m][0] + b0v, 0.f);
            float v1 = fmaxf(acc1[nt][m][1] + b1v, 0.f);
            float v2 = fmaxf(acc1[nt][m][2] + b0v, 0.f);
            float v3 = fmaxf(acc1[nt][m][3] + b1v, 0.f);
            unsigned h0 = pack_bf16x2(v0, v1);
            unsigned h1 = pack_bf16x2(v2, v3);
            sZ1h[rl * 132 + wx] = h0;
            sZ1l[rl * 132 + wx] = pack_bf16x2(v0 - bflo(h0), v1 - bfhi(h0));
            sZ1h[(rl + 8) * 132 + wx] = h1;
            sZ1l[(rl + 8) * 132 + wx] = pack_bf16x2(v2 - bflo(h1), v3 - bfhi(h1));
        }
    }
    __syncthreads();

    // ---- Layer 2: 256 -> 128 (16 k-chunks, warp n-slice = 16 cols) ------
    const int nb2 = warp * 16;
    float acc2[2][2][4];
    #pragma unroll
    for (int nt = 0; nt < 2; nt++)
        #pragma unroll
        for (int m = 0; m < 2; m++)
            acc2[nt][m][0] = acc2[nt][m][1] = acc2[nt][m][2] = acc2[nt][m][3] = 0.f;

    #pragma unroll
    for (int ks = 0; ks < 16; ks++) {
        unsigned ah[2][4], al[2][4];
        #pragma unroll
        for (int m = 0; m < 2; m++) {
            int rl = (m * 16 + gid) * 132, rh = rl + 8 * 132;
            int wi = ks * 8 + tig;
            ah[m][0] = sZ1h[rl + wi];     al[m][0] = sZ1l[rl + wi];
            ah[m][1] = sZ1h[rh + wi];     al[m][1] = sZ1l[rh + wi];
            ah[m][2] = sZ1h[rl + wi + 4]; al[m][2] = sZ1l[rl + wi + 4];
            ah[m][3] = sZ1h[rh + wi + 4]; al[m][3] = sZ1l[rh + wi + 4];
        }
        #pragma unroll
        for (int nt = 0; nt < 2; nt++) {
            int bi = (ks * 4 + tig) * 128 + nb2 + nt * 8 + gid;
            uint2 bh = __ldg(&g_P2h[bi]);
            uint2 bl = __ldg(&g_P2l[bi]);
            #pragma unroll
            for (int m = 0; m < 2; m++) {
                mma_bf16(acc2[nt][m], ah[m][0], ah[m][1], ah[m][2], ah[m][3], bh.x, bh.y);
                mma_bf16(acc2[nt][m], al[m][0], al[m][1], al[m][2], al[m][3], bh.x, bh.y);
                mma_bf16(acc2[nt][m], ah[m][0], ah[m][1], ah[m][2], ah[m][3], bl.x, bl.y);
            }
        }
    }
    // epilogue: relu(+bias) -> sZ2 (fp32)
    #pragma unroll
    for (int nt = 0; nt < 2; nt++) {
        int j0 = nb2 + nt * 8 + tig * 2;
        float b0v = __ldg(&mb2[j0]), b1v = __ldg(&mb2[j0 + 1]);
        #pragma unroll
        for (int m = 0; m < 2; m++) {
            int rl = m * 16 + gid;
            float2 zlo = make_float2(fmaxf(acc2[nt][m][0] + b0v, 0.f),
                                     fmaxf(acc2[nt][m][1] + b1v, 0.f));
            float2 zhi = make_float2(fmaxf(acc2[nt][m][2] + b0v, 0.f),
                                     fmaxf(acc2[nt][m][3] + b1v, 0.f));
            *(float2*)&sZ2[rl * 132 + j0] = zlo;
            *(float2*)&sZ2[(rl + 8) * 132 + j0] = zhi;
        }
    }
    __syncthreads();

    // ---- Layer 3: 128 -> 1 ----------------------------------------------
    {
        int row = tid >> 3, seg = tid & 7;
        float p = 0.f;
        #pragma unroll
        for (int k = seg * 16; k < seg * 16 + 16; k++)
            p += sZ2[row * 132 + k] * sW3[k];
        #pragma unroll
        for (int o = 4; o > 0; o >>= 1)
            p += __shfl_down_sync(0xFFFFFFFFu, p, o, 8);
        if (seg == 0) out[b0 + row] = p + mb3[0];
    }
}

// ---------------------------------------------------------------------------
extern "C" void kernel_launch(void* const* d_in, const int* in_sizes, int n_in,
                              void* d_out, int out_size) {
    const int*   customer_id  = (const int*)d_in[0];
    const int*   cand_good    = (const int*)d_in[1];
    const int*   cand_class   = (const int*)d_in[2];
    const int*   hist_goods   = (const int*)d_in[3];
    const int*   hist_classes = (const int*)d_in[4];
    const float* user_table   = (const float*)d_in[5];
    const float* item_table   = (const float*)d_in[6];
    const float* cat_table    = (const float*)d_in[7];
    const float* aw1 = (const float*)d_in[8];
    const float* ab1 = (const float*)d_in[9];
    const float* aw2 = (const float*)d_in[10];
    const float* ab2 = (const float*)d_in[11];
    const float* mw1 = (const float*)d_in[12];
    const float* mb1 = (const float*)d_in[13];
    const float* mw2 = (const float*)d_in[14];
    const float* mb2 = (const float*)d_in[15];
    const float* mw3 = (const float*)d_in[16];
    const float* mb3 = (const float*)d_in[17];

    const int smemA = 22352 * 4;   // 89408 B
    const int smemB = 18176 * 4;   // 72704 B
    cudaFuncSetAttribute(din_attention_kernel,
                         cudaFuncAttributeMaxDynamicSharedMemorySize, smemA);
    cudaFuncSetAttribute(din_mlp_kernel,
                         cudaFuncAttributeMaxDynamicSharedMemorySize, smemB);

    din_prep<<<40, 256>>>(aw1, aw2, mw1, mw2);

    din_attention_kernel<<<NB / GA, 256, smemA>>>(
        customer_id, cand_good, cand_class, hist_goods, hist_classes,
        user_table, item_table, cat_table, ab1, ab2);

    din_mlp_kernel<<<NB / 32, 256, smemB>>>(
        mb1, mb2, mw3, mb3, (float*)d_out);
}